// round 1
// baseline (speedup 1.0000x reference)
#include <cuda_runtime.h>
#include <cuda_bf16.h>

#define N_NODES 100000
#define E_EDGES 1600000
#define IN_CH   128
#define HID_CH  64
#define OUT_CH  32

// -------- scratch (device globals: no allocation allowed) --------
__device__ int   g_deg [N_NODES];
__device__ float g_dinv[N_NODES];
__device__ float g_h1  [N_NODES * HID_CH];   // x @ W1
__device__ float g_agg1[N_NODES * HID_CH];   // aggregated layer-1 (pre-relu)
__device__ float g_h2  [N_NODES * OUT_CH];   // relu(agg1) @ W2

// -------- degree / norm --------
__global__ void k_deg_init() {
    int i = blockIdx.x * blockDim.x + threadIdx.x;
    if (i < N_NODES) g_deg[i] = 1;            // self loop
}

__global__ void k_deg_count(const int* __restrict__ ei) {
    int e = blockIdx.x * blockDim.x + threadIdx.x;
    if (e < E_EDGES) atomicAdd(&g_deg[ei[E_EDGES + e]], 1);   // dst = row 1
}

__global__ void k_dinv() {
    int i = blockIdx.x * blockDim.x + threadIdx.x;
    if (i < N_NODES) g_dinv[i] = rsqrtf((float)g_deg[i]);
}

// -------- GEMM1: h1[N,64] = x[N,128] @ W1[128,64] --------
// 256 threads/block, 64 rows/block; thread = (row_local, colgrp of 16 cols)
__global__ void k_gemm1(const float* __restrict__ x, const float* __restrict__ W1) {
    __shared__ float Ws[IN_CH * HID_CH];       // 32 KB
    for (int i = threadIdx.x; i < IN_CH * HID_CH; i += blockDim.x) Ws[i] = W1[i];
    __syncthreads();

    int rl  = threadIdx.x >> 2;
    int cg  = (threadIdx.x & 3) * 16;
    int row = blockIdx.x * 64 + rl;
    if (row >= N_NODES) return;

    float acc[16];
#pragma unroll
    for (int j = 0; j < 16; j++) acc[j] = 0.f;

    const float4* xr = (const float4*)(x + (size_t)row * IN_CH);
#pragma unroll 4
    for (int k4 = 0; k4 < IN_CH / 4; k4++) {
        float4 xv = __ldg(xr + k4);
        const float* w0 = Ws + (k4 * 4) * HID_CH + cg;
#pragma unroll
        for (int j = 0; j < 16; j++) acc[j] = fmaf(xv.x, w0[j],             acc[j]);
#pragma unroll
        for (int j = 0; j < 16; j++) acc[j] = fmaf(xv.y, w0[HID_CH + j],    acc[j]);
#pragma unroll
        for (int j = 0; j < 16; j++) acc[j] = fmaf(xv.z, w0[2*HID_CH + j],  acc[j]);
#pragma unroll
        for (int j = 0; j < 16; j++) acc[j] = fmaf(xv.w, w0[3*HID_CH + j],  acc[j]);
    }
    float* o = g_h1 + (size_t)row * HID_CH + cg;
#pragma unroll
    for (int j = 0; j < 16; j++) o[j] = acc[j];
}

// -------- init agg1 with bias + self-loop term --------
__global__ void k_init_agg1(const float* __restrict__ b1) {
    int i = blockIdx.x * blockDim.x + threadIdx.x;
    if (i >= N_NODES * HID_CH) return;
    int node = i >> 6;          // /64
    int c    = i & 63;
    float di = g_dinv[node];
    g_agg1[i] = b1[c] + di * di * g_h1[i];
}

// -------- edge scatter layer 1: agg1[dst] += h1[src] * w  (vec4 red) --------
__global__ void k_scatter1(const int* __restrict__ ei) {
    int tid = blockIdx.x * blockDim.x + threadIdx.x;   // E*16 threads
    int e = tid >> 4;
    int c = (tid & 15) << 2;                            // float offset (16B aligned)
    if (e >= E_EDGES) return;
    int s = ei[e];
    int d = ei[E_EDGES + e];
    float w = g_dinv[s] * g_dinv[d];
    float4 v = *(const float4*)(g_h1 + (size_t)s * HID_CH + c);
    float* p = g_agg1 + (size_t)d * HID_CH + c;
    asm volatile("red.global.add.v4.f32 [%0], {%1,%2,%3,%4};"
                 :: "l"(p), "f"(v.x * w), "f"(v.y * w), "f"(v.z * w), "f"(v.w * w)
                 : "memory");
}

// -------- GEMM2: h2[N,32] = relu(agg1)[N,64] @ W2[64,32] --------
// 256 threads/block, 64 rows/block; A tile staged in smem (coalesced + relu)
__global__ void k_gemm2(const float* __restrict__ W2) {
    __shared__ float Ws[HID_CH * OUT_CH];      // 8 KB
    __shared__ float As[64 * HID_CH];          // 16 KB
    for (int i = threadIdx.x; i < HID_CH * OUT_CH; i += blockDim.x) Ws[i] = W2[i];

    int row0 = blockIdx.x * 64;
    for (int i = threadIdx.x; i < 64 * HID_CH; i += blockDim.x) {
        int r = row0 + (i >> 6);
        As[i] = (r < N_NODES) ? fmaxf(g_agg1[(size_t)r * HID_CH + (i & 63)], 0.f) : 0.f;
    }
    __syncthreads();

    int rl  = threadIdx.x >> 2;
    int cg  = (threadIdx.x & 3) * 8;
    int row = row0 + rl;
    if (row >= N_NODES) return;

    float acc[8];
#pragma unroll
    for (int j = 0; j < 8; j++) acc[j] = 0.f;

#pragma unroll 8
    for (int k = 0; k < HID_CH; k++) {
        float av = As[rl * HID_CH + k];
        const float* w = Ws + k * OUT_CH + cg;
#pragma unroll
        for (int j = 0; j < 8; j++) acc[j] = fmaf(av, w[j], acc[j]);
    }
    float* o = g_h2 + (size_t)row * OUT_CH + cg;
#pragma unroll
    for (int j = 0; j < 8; j++) o[j] = acc[j];
}

// -------- init out with bias + self-loop term --------
__global__ void k_init_out(const float* __restrict__ b2, float* __restrict__ out) {
    int i = blockIdx.x * blockDim.x + threadIdx.x;
    if (i >= N_NODES * OUT_CH) return;
    int node = i >> 5;          // /32
    int c    = i & 31;
    float di = g_dinv[node];
    out[i] = b2[c] + di * di * g_h2[i];
}

// -------- edge scatter layer 2 --------
__global__ void k_scatter2(const int* __restrict__ ei, float* __restrict__ out) {
    int tid = blockIdx.x * blockDim.x + threadIdx.x;   // E*8 threads
    int e = tid >> 3;
    int c = (tid & 7) << 2;
    if (e >= E_EDGES) return;
    int s = ei[e];
    int d = ei[E_EDGES + e];
    float w = g_dinv[s] * g_dinv[d];
    float4 v = *(const float4*)(g_h2 + (size_t)s * OUT_CH + c);
    float* p = out + (size_t)d * OUT_CH + c;
    asm volatile("red.global.add.v4.f32 [%0], {%1,%2,%3,%4};"
                 :: "l"(p), "f"(v.x * w), "f"(v.y * w), "f"(v.z * w), "f"(v.w * w)
                 : "memory");
}

static inline int cdiv(int a, int b) { return (a + b - 1) / b; }

extern "C" void kernel_launch(void* const* d_in, const int* in_sizes, int n_in,
                              void* d_out, int out_size) {
    const float* x  = (const float*)d_in[0];
    const int*   ei = (const int*)  d_in[1];
    const float* W1 = (const float*)d_in[2];
    const float* b1 = (const float*)d_in[3];
    const float* W2 = (const float*)d_in[4];
    const float* b2 = (const float*)d_in[5];
    float* out = (float*)d_out;

    k_deg_init <<<cdiv(N_NODES, 256), 256>>>();
    k_deg_count<<<cdiv(E_EDGES, 256), 256>>>(ei);
    k_dinv     <<<cdiv(N_NODES, 256), 256>>>();

    k_gemm1    <<<cdiv(N_NODES, 64), 256>>>(x, W1);
    k_init_agg1<<<cdiv(N_NODES * HID_CH, 256), 256>>>(b1);
    k_scatter1 <<<cdiv(E_EDGES * 16, 256), 256>>>(ei);

    k_gemm2    <<<cdiv(N_NODES, 64), 256>>>(W2);
    k_init_out <<<cdiv(N_NODES * OUT_CH, 256), 256>>>(b2, out);
    k_scatter2 <<<cdiv(E_EDGES * 8, 256), 256>>>(ei, out);
}

// round 2
// speedup vs baseline: 1.6208x; 1.6208x over previous
#include <cuda_runtime.h>
#include <cuda_bf16.h>

#define N_NODES 100000
#define E_EDGES 1600000
#define IN_CH   128
#define HID_CH  64
#define OUT_CH  32

typedef unsigned long long u64;

// -------- packed f32x2 helpers (Blackwell dual-fp32; PTX-only) --------
__device__ __forceinline__ u64 pack2(float lo, float hi) {
    u64 r; asm("mov.b64 %0, {%1, %2};" : "=l"(r) : "f"(lo), "f"(hi)); return r;
}
__device__ __forceinline__ u64 fma2(u64 a, u64 b, u64 c) {
    u64 d; asm("fma.rn.f32x2 %0, %1, %2, %3;" : "=l"(d) : "l"(a), "l"(b), "l"(c)); return d;
}

// -------- scratch (device globals: no allocation allowed) --------
__device__ int   g_deg [N_NODES];
__device__ float g_dinv[N_NODES];
__device__ float g_h1  [N_NODES * HID_CH];   // x @ W1
__device__ float g_agg1[N_NODES * HID_CH];   // aggregated layer-1 (pre-relu)
__device__ float g_h2  [N_NODES * OUT_CH];   // relu(agg1) @ W2

// -------- degree / norm --------
__global__ void k_deg_init() {
    int i = blockIdx.x * blockDim.x + threadIdx.x;
    if (i < N_NODES) g_deg[i] = 1;            // self loop
}

__global__ void k_deg_count(const int* __restrict__ ei) {
    int e = blockIdx.x * blockDim.x + threadIdx.x;
    if (e < E_EDGES) atomicAdd(&g_deg[ei[E_EDGES + e]], 1);   // dst = row 1
}

__global__ void k_dinv() {
    int i = blockIdx.x * blockDim.x + threadIdx.x;
    if (i < N_NODES) g_dinv[i] = rsqrtf((float)g_deg[i]);
}

// -------- GEMM1: h1[N,64] = x[N,128] @ W1[128,64], fused agg1 init --------
// 128 threads/block, 128 rows/block. Thread tile: 8 rows x 8 cols, f32x2 packed.
__global__ void __launch_bounds__(128, 2)
k_gemm1(const float* __restrict__ x, const float* __restrict__ W1,
        const float* __restrict__ b1) {
    __shared__ float Ws[IN_CH * HID_CH];       // 32 KB
    for (int i = threadIdx.x; i < IN_CH * HID_CH; i += 128) Ws[i] = W1[i];
    __syncthreads();

    int cg   = (threadIdx.x & 7) * 8;          // 8-col group
    int rl   = threadIdx.x >> 3;               // 0..15
    int row0 = blockIdx.x * 128 + rl * 8;

    u64 acc[8][4];
#pragma unroll
    for (int r = 0; r < 8; r++)
#pragma unroll
        for (int j = 0; j < 4; j++) acc[r][j] = 0ULL;

    const float4* xp[8];
#pragma unroll
    for (int r = 0; r < 8; r++) {
        int rr = row0 + r; if (rr >= N_NODES) rr = N_NODES - 1;
        xp[r] = (const float4*)(x + (size_t)rr * IN_CH);
    }

    for (int k4 = 0; k4 < IN_CH / 4; k4++) {
        float4 xv[8];
#pragma unroll
        for (int r = 0; r < 8; r++) xv[r] = __ldg(xp[r] + k4);
        const float* wbase = Ws + (k4 * 4) * HID_CH + cg;
#pragma unroll
        for (int kk = 0; kk < 4; kk++) {
            float4 wa = *(const float4*)(wbase + kk * HID_CH);
            float4 wb = *(const float4*)(wbase + kk * HID_CH + 4);
            u64 w0 = pack2(wa.x, wa.y), w1 = pack2(wa.z, wa.w);
            u64 w2 = pack2(wb.x, wb.y), w3 = pack2(wb.z, wb.w);
#pragma unroll
            for (int r = 0; r < 8; r++) {
                float xs = (kk == 0) ? xv[r].x : (kk == 1) ? xv[r].y
                         : (kk == 2) ? xv[r].z : xv[r].w;
                u64 xx = pack2(xs, xs);
                acc[r][0] = fma2(xx, w0, acc[r][0]);
                acc[r][1] = fma2(xx, w1, acc[r][1]);
                acc[r][2] = fma2(xx, w2, acc[r][2]);
                acc[r][3] = fma2(xx, w3, acc[r][3]);
            }
        }
    }

    float2 bv[4];
#pragma unroll
    for (int j = 0; j < 4; j++) bv[j] = *(const float2*)(b1 + cg + j * 2);

#pragma unroll
    for (int r = 0; r < 8; r++) {
        int rr = row0 + r;
        if (rr < N_NODES) {
            float di = g_dinv[rr];
            float di2 = di * di;
            u64* oh = (u64*)(g_h1   + (size_t)rr * HID_CH + cg);
            float2* oa = (float2*)(g_agg1 + (size_t)rr * HID_CH + cg);
#pragma unroll
            for (int j = 0; j < 4; j++) {
                oh[j] = acc[r][j];
                float2 f = *(float2*)&acc[r][j];
                float2 a;
                a.x = bv[j].x + di2 * f.x;
                a.y = bv[j].y + di2 * f.y;
                oa[j] = a;
            }
        }
    }
}

// -------- edge scatter layer 1: agg1[dst] += h1[src] * w  (vec4 red) --------
__global__ void k_scatter1(const int* __restrict__ ei) {
    int tid = blockIdx.x * blockDim.x + threadIdx.x;   // E*16 threads
    int e = tid >> 4;
    int c = (tid & 15) << 2;                            // float offset (16B aligned)
    if (e >= E_EDGES) return;
    int s = ei[e];
    int d = ei[E_EDGES + e];
    float w = g_dinv[s] * g_dinv[d];
    float4 v = *(const float4*)(g_h1 + (size_t)s * HID_CH + c);
    float* p = g_agg1 + (size_t)d * HID_CH + c;
    asm volatile("red.global.add.v4.f32 [%0], {%1,%2,%3,%4};"
                 :: "l"(p), "f"(v.x * w), "f"(v.y * w), "f"(v.z * w), "f"(v.w * w)
                 : "memory");
}

// -------- GEMM2: h2[N,32] = relu(agg1)[N,64] @ W2[64,32], fused out init ----
// 256 threads/block, 64 rows/block; A tile staged in smem (coalesced + relu)
__global__ void k_gemm2(const float* __restrict__ W2, const float* __restrict__ b2,
                        float* __restrict__ out) {
    __shared__ float Ws[HID_CH * OUT_CH];      // 8 KB
    __shared__ float As[64 * HID_CH];          // 16 KB
    for (int i = threadIdx.x; i < HID_CH * OUT_CH; i += blockDim.x) Ws[i] = W2[i];

    int row0 = blockIdx.x * 64;
    for (int i = threadIdx.x; i < 64 * HID_CH; i += blockDim.x) {
        int r = row0 + (i >> 6);
        As[i] = (r < N_NODES) ? fmaxf(g_agg1[(size_t)r * HID_CH + (i & 63)], 0.f) : 0.f;
    }
    __syncthreads();

    int rl  = threadIdx.x >> 2;
    int cg  = (threadIdx.x & 3) * 8;
    int row = row0 + rl;
    if (row >= N_NODES) return;

    u64 acc[4];
#pragma unroll
    for (int j = 0; j < 4; j++) acc[j] = 0ULL;

#pragma unroll 8
    for (int k = 0; k < HID_CH; k++) {
        float av = As[rl * HID_CH + k];
        u64 xx = pack2(av, av);
        const float* w = Ws + k * OUT_CH + cg;
        float4 wa = *(const float4*)(w);
        float4 wb = *(const float4*)(w + 4);
        acc[0] = fma2(xx, pack2(wa.x, wa.y), acc[0]);
        acc[1] = fma2(xx, pack2(wa.z, wa.w), acc[1]);
        acc[2] = fma2(xx, pack2(wb.x, wb.y), acc[2]);
        acc[3] = fma2(xx, pack2(wb.z, wb.w), acc[3]);
    }

    float di = g_dinv[row];
    float di2 = di * di;
    u64* oh = (u64*)(g_h2 + (size_t)row * OUT_CH + cg);
    float2* oo = (float2*)(out + (size_t)row * OUT_CH + cg);
#pragma unroll
    for (int j = 0; j < 4; j++) {
        oh[j] = acc[j];
        float2 f = *(float2*)&acc[j];
        float2 b = *(const float2*)(b2 + cg + j * 2);
        float2 a;
        a.x = b.x + di2 * f.x;
        a.y = b.y + di2 * f.y;
        oo[j] = a;
    }
}

// -------- edge scatter layer 2 --------
__global__ void k_scatter2(const int* __restrict__ ei, float* __restrict__ out) {
    int tid = blockIdx.x * blockDim.x + threadIdx.x;   // E*8 threads
    int e = tid >> 3;
    int c = (tid & 7) << 2;
    if (e >= E_EDGES) return;
    int s = ei[e];
    int d = ei[E_EDGES + e];
    float w = g_dinv[s] * g_dinv[d];
    float4 v = *(const float4*)(g_h2 + (size_t)s * OUT_CH + c);
    float* p = out + (size_t)d * OUT_CH + c;
    asm volatile("red.global.add.v4.f32 [%0], {%1,%2,%3,%4};"
                 :: "l"(p), "f"(v.x * w), "f"(v.y * w), "f"(v.z * w), "f"(v.w * w)
                 : "memory");
}

static inline int cdiv(int a, int b) { return (a + b - 1) / b; }

extern "C" void kernel_launch(void* const* d_in, const int* in_sizes, int n_in,
                              void* d_out, int out_size) {
    const float* x  = (const float*)d_in[0];
    const int*   ei = (const int*)  d_in[1];
    const float* W1 = (const float*)d_in[2];
    const float* b1 = (const float*)d_in[3];
    const float* W2 = (const float*)d_in[4];
    const float* b2 = (const float*)d_in[5];
    float* out = (float*)d_out;

    k_deg_init <<<cdiv(N_NODES, 256), 256>>>();
    k_deg_count<<<cdiv(E_EDGES, 256), 256>>>(ei);
    k_dinv     <<<cdiv(N_NODES, 256), 256>>>();

    k_gemm1    <<<cdiv(N_NODES, 128), 128>>>(x, W1, b1);
    k_scatter1 <<<cdiv(E_EDGES * 16, 256), 256>>>(ei);

    k_gemm2    <<<cdiv(N_NODES, 64), 256>>>(W2, b2, out);
    k_scatter2 <<<cdiv(E_EDGES * 8, 256), 256>>>(ei, out);
}

// round 3
// speedup vs baseline: 2.0559x; 1.2684x over previous
#include <cuda_runtime.h>
#include <cuda_bf16.h>

#define N_NODES 100000
#define E_EDGES 1600000
#define IN_CH   128
#define HID_CH  64
#define OUT_CH  32

#define SCAN_BLK 1024
#define SCAN_NB  ((N_NODES + SCAN_BLK - 1) / SCAN_BLK)   // 98

typedef unsigned long long u64;

// -------- packed f32x2 helpers (Blackwell dual-fp32; PTX-only) --------
__device__ __forceinline__ u64 pack2(float lo, float hi) {
    u64 r; asm("mov.b64 %0, {%1, %2};" : "=l"(r) : "f"(lo), "f"(hi)); return r;
}
__device__ __forceinline__ u64 fma2(u64 a, u64 b, u64 c) {
    u64 d; asm("fma.rn.f32x2 %0, %1, %2, %3;" : "=l"(d) : "l"(a), "l"(b), "l"(c)); return d;
}

// -------- scratch (device globals: no allocation allowed) --------
__device__ int   g_deg  [N_NODES];
__device__ float g_dinv [N_NODES];
__device__ int   g_off  [N_NODES];       // CSR row start (edges only, no self loop)
__device__ int   g_cur  [N_NODES];       // atomic fill cursors
__device__ int   g_csr  [E_EDGES];       // src node per CSR slot
__device__ int   g_bsum [SCAN_NB];
__device__ int   g_bpre [SCAN_NB];
__device__ float g_h1   [N_NODES * HID_CH];   // x @ W1
__device__ float g_agg1 [N_NODES * HID_CH];   // relu(aggregated layer 1)
__device__ float g_h2   [N_NODES * OUT_CH];   // relu(agg1) @ W2

// -------- degree / norm --------
__global__ void k_deg_init() {
    int i = blockIdx.x * blockDim.x + threadIdx.x;
    if (i < N_NODES) g_deg[i] = 1;            // self loop
}

__global__ void k_deg_count(const int* __restrict__ ei) {
    int e = blockIdx.x * blockDim.x + threadIdx.x;
    if (e < E_EDGES) atomicAdd(&g_deg[ei[E_EDGES + e]], 1);   // dst = row 1
}

__global__ void k_dinv() {
    int i = blockIdx.x * blockDim.x + threadIdx.x;
    if (i < N_NODES) g_dinv[i] = rsqrtf((float)g_deg[i]);
}

// -------- exclusive scan of (deg-1) over nodes: 3-phase --------
__global__ void k_scan1() {            // per-block sums
    int idx = blockIdx.x * SCAN_BLK + threadIdx.x;
    int v = (idx < N_NODES) ? (g_deg[idx] - 1) : 0;
    __shared__ int ws[32];
    int lane = threadIdx.x & 31, wid = threadIdx.x >> 5;
#pragma unroll
    for (int o = 16; o > 0; o >>= 1) v += __shfl_down_sync(0xffffffffu, v, o);
    if (lane == 0) ws[wid] = v;
    __syncthreads();
    if (wid == 0) {
        int s = ws[lane];
#pragma unroll
        for (int o = 16; o > 0; o >>= 1) s += __shfl_down_sync(0xffffffffu, s, o);
        if (lane == 0) g_bsum[blockIdx.x] = s;
    }
}

__global__ void k_scan2() {            // tiny serial scan over block sums
    if (threadIdx.x == 0) {
        int acc = 0;
        for (int b = 0; b < SCAN_NB; b++) { int t = g_bsum[b]; g_bpre[b] = acc; acc += t; }
    }
}

__global__ void k_scan3() {            // block exclusive scan + offsets
    int idx = blockIdx.x * SCAN_BLK + threadIdx.x;
    int v = (idx < N_NODES) ? (g_deg[idx] - 1) : 0;
    int lane = threadIdx.x & 31, wid = threadIdx.x >> 5;
    int inc = v;
#pragma unroll
    for (int o = 1; o < 32; o <<= 1) {
        int u = __shfl_up_sync(0xffffffffu, inc, o);
        if (lane >= o) inc += u;
    }
    __shared__ int ws[32];
    if (lane == 31) ws[wid] = inc;
    __syncthreads();
    if (wid == 0) {
        int s = ws[lane];
#pragma unroll
        for (int o = 1; o < 32; o <<= 1) {
            int u = __shfl_up_sync(0xffffffffu, s, o);
            if (lane >= o) s += u;
        }
        ws[lane] = s;                 // inclusive warp sums
    }
    __syncthreads();
    int woff = (wid == 0) ? 0 : ws[wid - 1];
    int ex = inc - v + woff + g_bpre[blockIdx.x];
    if (idx < N_NODES) { g_off[idx] = ex; g_cur[idx] = ex; }
}

// -------- CSR fill: slot per (dst) edge holds src --------
__global__ void k_csr_fill(const int* __restrict__ ei) {
    int e = blockIdx.x * blockDim.x + threadIdx.x;
    if (e >= E_EDGES) return;
    int s = ei[e];
    int d = ei[E_EDGES + e];
    int pos = atomicAdd(&g_cur[d], 1);
    g_csr[pos] = s;
}

// -------- GEMM1: h1[N,64] = x[N,128] @ W1[128,64] --------
// 128 threads/block, 128 rows/block. Thread tile: 8 rows x 8 cols, f32x2 packed.
__global__ void __launch_bounds__(128, 3)
k_gemm1(const float* __restrict__ x, const float* __restrict__ W1) {
    __shared__ float Ws[IN_CH * HID_CH];       // 32 KB
    for (int i = threadIdx.x; i < IN_CH * HID_CH; i += 128) Ws[i] = W1[i];
    __syncthreads();

    int cg   = (threadIdx.x & 7) * 8;          // 8-col group
    int rl   = threadIdx.x >> 3;               // 0..15
    int row0 = blockIdx.x * 128 + rl * 8;

    u64 acc[8][4];
#pragma unroll
    for (int r = 0; r < 8; r++)
#pragma unroll
        for (int j = 0; j < 4; j++) acc[r][j] = 0ULL;

    const float4* xp[8];
#pragma unroll
    for (int r = 0; r < 8; r++) {
        int rr = row0 + r; if (rr >= N_NODES) rr = N_NODES - 1;
        xp[r] = (const float4*)(x + (size_t)rr * IN_CH);
    }

    for (int k4 = 0; k4 < IN_CH / 4; k4++) {
        float4 xv[8];
#pragma unroll
        for (int r = 0; r < 8; r++) xv[r] = __ldg(xp[r] + k4);
        const float* wbase = Ws + (k4 * 4) * HID_CH + cg;
#pragma unroll
        for (int kk = 0; kk < 4; kk++) {
            float4 wa = *(const float4*)(wbase + kk * HID_CH);
            float4 wb = *(const float4*)(wbase + kk * HID_CH + 4);
            u64 w0 = pack2(wa.x, wa.y), w1 = pack2(wa.z, wa.w);
            u64 w2 = pack2(wb.x, wb.y), w3 = pack2(wb.z, wb.w);
#pragma unroll
            for (int r = 0; r < 8; r++) {
                float xs = (kk == 0) ? xv[r].x : (kk == 1) ? xv[r].y
                         : (kk == 2) ? xv[r].z : xv[r].w;
                u64 xx = pack2(xs, xs);
                acc[r][0] = fma2(xx, w0, acc[r][0]);
                acc[r][1] = fma2(xx, w1, acc[r][1]);
                acc[r][2] = fma2(xx, w2, acc[r][2]);
                acc[r][3] = fma2(xx, w3, acc[r][3]);
            }
        }
    }

#pragma unroll
    for (int r = 0; r < 8; r++) {
        int rr = row0 + r;
        if (rr < N_NODES) {
            u64* oh = (u64*)(g_h1 + (size_t)rr * HID_CH + cg);
#pragma unroll
            for (int j = 0; j < 4; j++) oh[j] = acc[r][j];
        }
    }
}

// -------- layer-1 aggregation (CSR gather): agg1 = relu(b1 + dinv^2 h1 + sum) --
// warp per node; half-warp per edge; 16 lanes x float4 = 64 cols
__global__ void k_agg1(const float* __restrict__ b1) {
    int warp = (blockIdx.x * blockDim.x + threadIdx.x) >> 5;
    if (warp >= N_NODES) return;
    int lane = threadIdx.x & 31;
    int half = lane >> 4;
    int c    = (lane & 15) * 4;

    int start = g_off[warp];
    int end   = start + g_deg[warp] - 1;
    float dn  = g_dinv[warp];

    float4 acc = make_float4(0.f, 0.f, 0.f, 0.f);
    for (int i = start + half; i < end; i += 2) {
        int s   = g_csr[i];
        float w = g_dinv[s] * dn;
        float4 v = *(const float4*)(g_h1 + (size_t)s * HID_CH + c);
        acc.x += v.x * w; acc.y += v.y * w; acc.z += v.z * w; acc.w += v.w * w;
    }
    acc.x += __shfl_xor_sync(0xffffffffu, acc.x, 16);
    acc.y += __shfl_xor_sync(0xffffffffu, acc.y, 16);
    acc.z += __shfl_xor_sync(0xffffffffu, acc.z, 16);
    acc.w += __shfl_xor_sync(0xffffffffu, acc.w, 16);

    if (half == 0) {
        float di2 = dn * dn;
        float4 hs = *(const float4*)(g_h1 + (size_t)warp * HID_CH + c);
        float4 bv = *(const float4*)(b1 + c);
        float4 o;
        o.x = fmaxf(bv.x + di2 * hs.x + acc.x, 0.f);
        o.y = fmaxf(bv.y + di2 * hs.y + acc.y, 0.f);
        o.z = fmaxf(bv.z + di2 * hs.z + acc.z, 0.f);
        o.w = fmaxf(bv.w + di2 * hs.w + acc.w, 0.f);
        *(float4*)(g_agg1 + (size_t)warp * HID_CH + c) = o;
    }
}

// -------- GEMM2: h2[N,32] = agg1[N,64] @ W2[64,32] (agg1 already relu'd) ----
__global__ void k_gemm2(const float* __restrict__ W2) {
    __shared__ float Ws[HID_CH * OUT_CH];      // 8 KB
    __shared__ float As[64 * HID_CH];          // 16 KB
    for (int i = threadIdx.x; i < HID_CH * OUT_CH; i += blockDim.x) Ws[i] = W2[i];

    int row0 = blockIdx.x * 64;
    for (int i = threadIdx.x; i < 64 * HID_CH; i += blockDim.x) {
        int r = row0 + (i >> 6);
        As[i] = (r < N_NODES) ? g_agg1[(size_t)r * HID_CH + (i & 63)] : 0.f;
    }
    __syncthreads();

    int rl  = threadIdx.x >> 2;
    int cg  = (threadIdx.x & 3) * 8;
    int row = row0 + rl;
    if (row >= N_NODES) return;

    u64 acc[4];
#pragma unroll
    for (int j = 0; j < 4; j++) acc[j] = 0ULL;

#pragma unroll 8
    for (int k = 0; k < HID_CH; k++) {
        float av = As[rl * HID_CH + k];
        u64 xx = pack2(av, av);
        const float* w = Ws + k * OUT_CH + cg;
        float4 wa = *(const float4*)(w);
        float4 wb = *(const float4*)(w + 4);
        acc[0] = fma2(xx, pack2(wa.x, wa.y), acc[0]);
        acc[1] = fma2(xx, pack2(wa.z, wa.w), acc[1]);
        acc[2] = fma2(xx, pack2(wb.x, wb.y), acc[2]);
        acc[3] = fma2(xx, pack2(wb.z, wb.w), acc[3]);
    }

    u64* oh = (u64*)(g_h2 + (size_t)row * OUT_CH + cg);
#pragma unroll
    for (int j = 0; j < 4; j++) oh[j] = acc[j];
}

// -------- layer-2 aggregation (CSR gather): out = b2 + dinv^2 h2 + sum ------
// warp per node; quarter-warp per edge; 8 lanes x float4 = 32 cols
__global__ void k_agg2(const float* __restrict__ b2, float* __restrict__ out) {
    int warp = (blockIdx.x * blockDim.x + threadIdx.x) >> 5;
    if (warp >= N_NODES) return;
    int lane = threadIdx.x & 31;
    int q    = lane >> 3;
    int c    = (lane & 7) * 4;

    int start = g_off[warp];
    int end   = start + g_deg[warp] - 1;
    float dn  = g_dinv[warp];

    float4 acc = make_float4(0.f, 0.f, 0.f, 0.f);
    for (int i = start + q; i < end; i += 4) {
        int s   = g_csr[i];
        float w = g_dinv[s] * dn;
        float4 v = *(const float4*)(g_h2 + (size_t)s * OUT_CH + c);
        acc.x += v.x * w; acc.y += v.y * w; acc.z += v.z * w; acc.w += v.w * w;
    }
#pragma unroll
    for (int o = 8; o <= 16; o <<= 1) {
        acc.x += __shfl_xor_sync(0xffffffffu, acc.x, o);
        acc.y += __shfl_xor_sync(0xffffffffu, acc.y, o);
        acc.z += __shfl_xor_sync(0xffffffffu, acc.z, o);
        acc.w += __shfl_xor_sync(0xffffffffu, acc.w, o);
    }

    if (q == 0) {
        float di2 = dn * dn;
        float4 hs = *(const float4*)(g_h2 + (size_t)warp * OUT_CH + c);
        float4 bv = *(const float4*)(b2 + c);
        float4 o;
        o.x = bv.x + di2 * hs.x + acc.x;
        o.y = bv.y + di2 * hs.y + acc.y;
        o.z = bv.z + di2 * hs.z + acc.z;
        o.w = bv.w + di2 * hs.w + acc.w;
        *(float4*)(out + (size_t)warp * OUT_CH + c) = o;
    }
}

static inline int cdiv(int a, int b) { return (a + b - 1) / b; }

extern "C" void kernel_launch(void* const* d_in, const int* in_sizes, int n_in,
                              void* d_out, int out_size) {
    const float* x  = (const float*)d_in[0];
    const int*   ei = (const int*)  d_in[1];
    const float* W1 = (const float*)d_in[2];
    const float* b1 = (const float*)d_in[3];
    const float* W2 = (const float*)d_in[4];
    const float* b2 = (const float*)d_in[5];
    float* out = (float*)d_out;

    k_deg_init <<<cdiv(N_NODES, 256), 256>>>();
    k_deg_count<<<cdiv(E_EDGES, 256), 256>>>(ei);
    k_dinv     <<<cdiv(N_NODES, 256), 256>>>();

    k_scan1    <<<SCAN_NB, SCAN_BLK>>>();
    k_scan2    <<<1, 32>>>();
    k_scan3    <<<SCAN_NB, SCAN_BLK>>>();
    k_csr_fill <<<cdiv(E_EDGES, 256), 256>>>(ei);

    k_gemm1    <<<cdiv(N_NODES, 128), 128>>>(x, W1);
    k_agg1     <<<cdiv(N_NODES * 32, 256), 256>>>(b1);

    k_gemm2    <<<cdiv(N_NODES, 64), 256>>>(W2);
    k_agg2     <<<cdiv(N_NODES * 32, 256), 256>>>(b2, out);
}